// round 15
// baseline (speedup 1.0000x reference)
#include <cuda_runtime.h>
#include <cuda_bf16.h>
#include <cuda_fp16.h>
#include <cstdint>

#define N_NODES 50000
#define N_EDGES 600000
#define N_GRAPHS 1000
#define HID 128
#define NEG_SLOPE 0.01f
#define HALF_N 25000

#define SCH 16
#define SCAN_T 256
#define SCAN_TILE (SCAN_T * SCH)
#define SCAN_B ((N_NODES + SCAN_TILE - 1) / SCAN_TILE)   // 13

// ---------------- scratch (static device globals; no allocation) ----------------
__device__ __half g_bufH [(size_t)N_NODES * HID];  // layer-1 GEMM output (prescaled), fp16
__device__ __half g_bufH2[(size_t)N_NODES * HID];  // layer-2 GEMM output (prescaled), fp16
__device__ __half g_bufC [(size_t)N_NODES * HID];  // layer-1 activated output, fp16
__device__ float  g_pool[N_GRAPHS * HID];
__device__ float  g_cnt[N_GRAPHS];
__device__ int    g_count[N_NODES];
__device__ int    g_rowptr[N_NODES + 1];
__device__ int    g_cursor[N_NODES];
__device__ int    g_csr_src[N_EDGES];
__device__ unsigned long long g_tilestate[32];
__device__ __nv_bfloat16 g_wt_hi[2][HID * HID];
__device__ __nv_bfloat16 g_wt_lo[2][HID * HID];

// ---------------- helpers ----------------
__device__ __forceinline__ float leaky(float x) {
    return x > 0.0f ? x : NEG_SLOPE * x;
}

__device__ __forceinline__ float dinv_of(int c) {
    return rsqrtf((float)c + 1.0f);
}

__device__ __forceinline__ void red_add_v4(float* addr, float a, float b, float c, float d) {
    asm volatile("red.global.add.v4.f32 [%0], {%1, %2, %3, %4};"
                 :: "l"(addr), "f"(a), "f"(b), "f"(c), "f"(d) : "memory");
}

__device__ __forceinline__ float4 ld_half4(const __half* p) {
    uint2 u = __ldg((const uint2*)p);
    __half2 h0 = *reinterpret_cast<__half2*>(&u.x);
    __half2 h1 = *reinterpret_cast<__half2*>(&u.y);
    float2 f0 = __half22float2(h0);
    float2 f1 = __half22float2(h1);
    return make_float4(f0.x, f0.y, f1.x, f1.y);
}

__device__ __forceinline__ void mma_bf16(float* d,
                                         uint32_t a0, uint32_t a1, uint32_t a2, uint32_t a3,
                                         uint32_t b0, uint32_t b1) {
    asm volatile("mma.sync.aligned.m16n8k16.row.col.f32.bf16.bf16.f32 "
                 "{%0,%1,%2,%3}, {%4,%5,%6,%7}, {%8,%9}, {%0,%1,%2,%3};"
                 : "+f"(d[0]), "+f"(d[1]), "+f"(d[2]), "+f"(d[3])
                 : "r"(a0), "r"(a1), "r"(a2), "r"(a3), "r"(b0), "r"(b1));
}

// ---------------- init ----------------
__global__ void init_kernel(float* pool, float* cnt, int* count,
                            unsigned long long* tilestate) {
    int i = blockIdx.x * blockDim.x + threadIdx.x;
    if (i < N_GRAPHS * HID) pool[i] = 0.0f;
    if (i < N_NODES) count[i] = 0;
    if (i < N_GRAPHS) cnt[i] = 0.0f;
    if (i < 32) tilestate[i] = 0ull;
}

// ---------------- degree histogram over dst ----------------
__global__ void hist_kernel(const int* __restrict__ dst, int* __restrict__ count) {
    int t = blockIdx.x * blockDim.x + threadIdx.x;
    if (t >= N_EDGES / 4) return;
    int4 d = __ldg((const int4*)dst + t);
    atomicAdd(&count[d.x], 1);
    atomicAdd(&count[d.y], 1);
    atomicAdd(&count[d.z], 1);
    atomicAdd(&count[d.w], 1);
}

// ---------------- single-pass scan (1-window lookback) ----------------
__global__ __launch_bounds__(SCAN_T) void scan_fused_kernel(
    const int* __restrict__ count,
    int* __restrict__ rowptr, int* __restrict__ cursor,
    unsigned long long* __restrict__ tilestate)
{
    __shared__ int warptot[SCAN_T / 32];
    __shared__ int s_base;
    const int bid = blockIdx.x;
    const int tid = threadIdx.x;
    const int base = bid * SCAN_TILE + tid * SCH;

    int pre[SCH];
    int s = 0;
#pragma unroll
    for (int q = 0; q < SCH; q++) {
        int idx = base + q;
        int c = (idx < N_NODES) ? __ldg(count + idx) : 0;
        pre[q] = s;
        s += c;
    }

    int lane = tid & 31, w = tid >> 5;
    int x = s;
#pragma unroll
    for (int off = 1; off < 32; off <<= 1) {
        int y = __shfl_up_sync(0xffffffffu, x, off);
        if (lane >= off) x += y;
    }
    if (lane == 31) warptot[w] = x;
    __syncthreads();
    if (tid < SCAN_T / 32) {
        int t2 = warptot[tid];
#pragma unroll
        for (int off = 1; off < SCAN_T / 32; off <<= 1) {
            int y = __shfl_up_sync(0xffu, t2, off);
            if ((int)tid >= off) t2 += y;
        }
        warptot[tid] = t2;
    }
    __syncthreads();
    int thread_excl = x - s + (w > 0 ? warptot[w - 1] : 0);
    int S = warptot[SCAN_T / 32 - 1];

    if (tid == 0) {
        unsigned long long pk = (bid == 0)
            ? ((2ull << 32) | (unsigned int)S)
            : ((1ull << 32) | (unsigned int)S);
        atomicExch(&tilestate[bid], pk);
        if (bid == 0) s_base = 0;
    }

    if (bid > 0 && w == 0) {
        int k = bid - 1 - lane;
        unsigned long long pk;
        int st, val;
        do {
            pk = (k >= 0) ? *((volatile unsigned long long*)&tilestate[k]) : (2ull << 32);
            st = (int)(pk >> 32);
            val = (int)(unsigned int)pk;
        } while (__any_sync(0xffffffffu, st == 0) || !__ballot_sync(0xffffffffu, st == 2));
        unsigned pm = __ballot_sync(0xffffffffu, st == 2);
        int L = __ffs(pm) - 1;
        int contrib = (lane <= L) ? val : 0;
#pragma unroll
        for (int off = 16; off > 0; off >>= 1)
            contrib += __shfl_down_sync(0xffffffffu, contrib, off);
        int base2 = __shfl_sync(0xffffffffu, contrib, 0);
        if (lane == 0) {
            s_base = base2;
            atomicExch(&tilestate[bid], (2ull << 32) | (unsigned int)(base2 + S));
        }
    }
    __syncthreads();

    int excl0 = s_base + thread_excl;
#pragma unroll
    for (int q = 0; q < SCH; q++) {
        int idx = base + q;
        if (idx < N_NODES) {
            rowptr[idx] = excl0 + pre[q];
            cursor[idx] = excl0 + pre[q];
        }
    }
    if (bid == 0 && tid == 0) rowptr[N_NODES] = N_EDGES;
}

// ---------------- fill CSR: 1 edge/thread ----------------
__global__ void fill_kernel(const int* __restrict__ src, const int* __restrict__ dst,
                            int* __restrict__ cursor, int* __restrict__ csr_src)
{
    int e = blockIdx.x * blockDim.x + threadIdx.x;
    if (e >= N_EDGES) return;
    int s = __ldg(src + e);
    int d = __ldg(dst + e);
    int p = atomicAdd(&cursor[d], 1);
    csr_src[p] = s;
}

// ---------------- W prep (both layers; blockIdx.y = layer) ----------------
__global__ void wprep_kernel(const float* __restrict__ W1, const float* __restrict__ W2,
                             __nv_bfloat16* __restrict__ wt_hi,
                             __nv_bfloat16* __restrict__ wt_lo)
{
    int i = blockIdx.x * blockDim.x + threadIdx.x;
    if (i >= HID * HID) return;
    int layer = blockIdx.y;
    const float* W = layer ? W2 : W1;
    int n = i & 127, k = i >> 7;
    float v = W[i];
    __nv_bfloat16 h = __float2bfloat16(v);
    wt_hi[layer * HID * HID + n * HID + k] = h;
    wt_lo[layer * HID * HID + n * HID + k] = __float2bfloat16(v - __bfloat162float(h));
}

// ---------------- warp-MMA GEMM: H'(fp16) = dinv * (X*W), row range [rowOff, M) --------
#define AS 132
#define SM_AH 0
#define SM_AL (SM_AH + 128 * AS * 2)
#define SM_BH (SM_AL + 128 * AS * 2)
#define SM_BL (SM_BH + 128 * AS * 2)
#define SM_GEMM_TOTAL (SM_BL + 128 * AS * 2)   // 135168 B

template <bool FP16IN>
__global__ __launch_bounds__(256) void gemm_mma_kernel(
    const void* __restrict__ Xv,
    const __nv_bfloat16* __restrict__ wt_hi,
    const __nv_bfloat16* __restrict__ wt_lo,
    const int* __restrict__ count,
    __half* __restrict__ H, int rowOff, int M)
{
    extern __shared__ char smem[];
    const int tid = threadIdx.x;
    const int wid = tid >> 5;
    const int lane = tid & 31;
    const int rowBase = rowOff + blockIdx.x * 128;

    {
        int row = tid >> 1;
        int half_ = tid & 1;
        int gr = rowBase + row;
        char* ah = smem + SM_AH + row * (AS * 2) + half_ * 128;
        char* al = smem + SM_AL + row * (AS * 2) + half_ * 128;
#pragma unroll
        for (int k4 = 0; k4 < 16; k4++) {
            float4 v;
            if (FP16IN) {
                const __half* xr = (const __half*)Xv + (size_t)gr * HID + half_ * 64;
                if (gr < M) v = ld_half4(xr + k4 * 4);
                else v = make_float4(0.f, 0.f, 0.f, 0.f);
            } else {
                const float4* xr = (const float4*)((const float*)Xv + (size_t)gr * HID) + half_ * 16;
                v = (gr < M) ? __ldg(&xr[k4]) : make_float4(0.f, 0.f, 0.f, 0.f);
            }
            __nv_bfloat16 h0 = __float2bfloat16(v.x), h1 = __float2bfloat16(v.y);
            __nv_bfloat16 h2 = __float2bfloat16(v.z), h3 = __float2bfloat16(v.w);
            __nv_bfloat16 l0 = __float2bfloat16(v.x - __bfloat162float(h0));
            __nv_bfloat16 l1 = __float2bfloat16(v.y - __bfloat162float(h1));
            __nv_bfloat16 l2 = __float2bfloat16(v.z - __bfloat162float(h2));
            __nv_bfloat16 l3 = __float2bfloat16(v.w - __bfloat162float(h3));
            uint2 hp, lp;
            hp.x = (uint32_t)__bfloat16_as_ushort(h0) | ((uint32_t)__bfloat16_as_ushort(h1) << 16);
            hp.y = (uint32_t)__bfloat16_as_ushort(h2) | ((uint32_t)__bfloat16_as_ushort(h3) << 16);
            lp.x = (uint32_t)__bfloat16_as_ushort(l0) | ((uint32_t)__bfloat16_as_ushort(l1) << 16);
            lp.y = (uint32_t)__bfloat16_as_ushort(l2) | ((uint32_t)__bfloat16_as_ushort(l3) << 16);
            *(uint2*)(ah + k4 * 8) = hp;
            *(uint2*)(al + k4 * 8) = lp;
        }
    }
    {
        const uint32_t* gh = (const uint32_t*)wt_hi;
        const uint32_t* gl = (const uint32_t*)wt_lo;
#pragma unroll
        for (int w = 0; w < 32; w++) {
            int wi = tid + w * 256;
            int r = wi >> 6, c = wi & 63;
            *(uint32_t*)(smem + SM_BH + r * (AS * 2) + c * 4) = __ldg(&gh[r * 64 + c]);
            *(uint32_t*)(smem + SM_BL + r * (AS * 2) + c * 4) = __ldg(&gl[r * 64 + c]);
        }
    }
    __syncthreads();

    const int g = lane >> 2, t = lane & 3;
    const int mOff = (wid & 3) * 32;
    const int nOff = (wid >> 2) * 64;

    float acc[2][8][4];
#pragma unroll
    for (int i = 0; i < 2; i++)
#pragma unroll
        for (int j = 0; j < 8; j++)
#pragma unroll
            for (int q = 0; q < 4; q++) acc[i][j][q] = 0.0f;

#pragma unroll
    for (int ks = 0; ks < 8; ks++) {
        int k0 = ks * 16;
        uint32_t ah[2][4], al[2][4];
#pragma unroll
        for (int i = 0; i < 2; i++) {
            int r0 = mOff + i * 16 + g;
            const char* pah = smem + SM_AH;
            const char* pal = smem + SM_AL;
            ah[i][0] = *(const uint32_t*)(pah + (r0)     * (AS * 2) + (k0 + t * 2) * 2);
            ah[i][1] = *(const uint32_t*)(pah + (r0 + 8) * (AS * 2) + (k0 + t * 2) * 2);
            ah[i][2] = *(const uint32_t*)(pah + (r0)     * (AS * 2) + (k0 + t * 2 + 8) * 2);
            ah[i][3] = *(const uint32_t*)(pah + (r0 + 8) * (AS * 2) + (k0 + t * 2 + 8) * 2);
            al[i][0] = *(const uint32_t*)(pal + (r0)     * (AS * 2) + (k0 + t * 2) * 2);
            al[i][1] = *(const uint32_t*)(pal + (r0 + 8) * (AS * 2) + (k0 + t * 2) * 2);
            al[i][2] = *(const uint32_t*)(pal + (r0)     * (AS * 2) + (k0 + t * 2 + 8) * 2);
            al[i][3] = *(const uint32_t*)(pal + (r0 + 8) * (AS * 2) + (k0 + t * 2 + 8) * 2);
        }
#pragma unroll
        for (int j = 0; j < 8; j++) {
            int n0 = nOff + j * 8 + g;
            uint32_t bh0 = *(const uint32_t*)(smem + SM_BH + n0 * (AS * 2) + (k0 + t * 2) * 2);
            uint32_t bh1 = *(const uint32_t*)(smem + SM_BH + n0 * (AS * 2) + (k0 + t * 2 + 8) * 2);
            uint32_t bl0 = *(const uint32_t*)(smem + SM_BL + n0 * (AS * 2) + (k0 + t * 2) * 2);
            uint32_t bl1 = *(const uint32_t*)(smem + SM_BL + n0 * (AS * 2) + (k0 + t * 2 + 8) * 2);
#pragma unroll
            for (int i = 0; i < 2; i++) {
                mma_bf16(acc[i][j], ah[i][0], ah[i][1], ah[i][2], ah[i][3], bh0, bh1);
                mma_bf16(acc[i][j], ah[i][0], ah[i][1], ah[i][2], ah[i][3], bl0, bl1);
                mma_bf16(acc[i][j], al[i][0], al[i][1], al[i][2], al[i][3], bh0, bh1);
            }
        }
    }

#pragma unroll
    for (int i = 0; i < 2; i++) {
        int row = rowBase + mOff + i * 16 + g;
        float d0 = (row < M) ? dinv_of(__ldg(count + row)) : 0.0f;
        float d1 = (row + 8 < M) ? dinv_of(__ldg(count + row + 8)) : 0.0f;
#pragma unroll
        for (int j = 0; j < 8; j++) {
            int col = nOff + j * 8 + t * 2;
            if (row < M)
                *(__half2*)(H + (size_t)row * HID + col) =
                    __floats2half2_rn(acc[i][j][0] * d0, acc[i][j][1] * d0);
            if (row + 8 < M)
                *(__half2*)(H + (size_t)(row + 8) * HID + col) =
                    __floats2half2_rn(acc[i][j][2] * d1, acc[i][j][3] * d1);
        }
    }
}

// ---------------- gather core ----------------
__device__ __forceinline__ float4 gather_node(
    const __half* __restrict__ H, const int* __restrict__ rowptr,
    const int* __restrict__ csr_src, const int* __restrict__ count,
    const float* __restrict__ bias, int n, int lane)
{
    float4 acc = ld_half4(H + (size_t)n * HID + lane * 4);

    int i   = __ldg(rowptr + n);
    int end = __ldg(rowptr + n + 1);

    for (; i + 4 <= end; i += 4) {
        int s0 = __ldg(csr_src + i + 0);
        int s1 = __ldg(csr_src + i + 1);
        int s2 = __ldg(csr_src + i + 2);
        int s3 = __ldg(csr_src + i + 3);
        float4 v0 = ld_half4(H + (size_t)s0 * HID + lane * 4);
        float4 v1 = ld_half4(H + (size_t)s1 * HID + lane * 4);
        float4 v2 = ld_half4(H + (size_t)s2 * HID + lane * 4);
        float4 v3 = ld_half4(H + (size_t)s3 * HID + lane * 4);
        acc.x += v0.x + v1.x + v2.x + v3.x;
        acc.y += v0.y + v1.y + v2.y + v3.y;
        acc.z += v0.z + v1.z + v2.z + v3.z;
        acc.w += v0.w + v1.w + v2.w + v3.w;
    }
    for (; i < end; i++) {
        int s = __ldg(csr_src + i);
        float4 v = ld_half4(H + (size_t)s * HID + lane * 4);
        acc.x += v.x; acc.y += v.y; acc.z += v.z; acc.w += v.w;
    }

    float dn = dinv_of(__ldg(count + n));
    float4 b = *(const float4*)(bias + lane * 4);
    acc.x = leaky(fmaf(dn, acc.x, b.x));
    acc.y = leaky(fmaf(dn, acc.y, b.y));
    acc.z = leaky(fmaf(dn, acc.z, b.z));
    acc.w = leaky(fmaf(dn, acc.w, b.w));
    return acc;
}

// layer-1 gather over node range [nodeOff, nHi)
__global__ __launch_bounds__(256) void gather_kernel(
    const __half* __restrict__ H, __half* __restrict__ OUT,
    const int* __restrict__ rowptr, const int* __restrict__ csr_src,
    const int* __restrict__ count, const float* __restrict__ bias,
    int nodeOff, int nHi)
{
    int n = nodeOff + blockIdx.x * 8 + (threadIdx.x >> 5);
    int lane = threadIdx.x & 31;
    if (n >= nHi) return;
    float4 acc = gather_node(H, rowptr, csr_src, count, bias, n, lane);
    __half2 o0 = __floats2half2_rn(acc.x, acc.y);
    __half2 o1 = __floats2half2_rn(acc.z, acc.w);
    uint2 u;
    u.x = *reinterpret_cast<uint32_t*>(&o0);
    u.y = *reinterpret_cast<uint32_t*>(&o1);
    *(uint2*)(OUT + (size_t)n * HID + lane * 4) = u;
}

// layer-2 gather fused with mean-pool accumulation
__global__ __launch_bounds__(256) void gather_pool_kernel(
    const __half* __restrict__ H,
    const int* __restrict__ rowptr, const int* __restrict__ csr_src,
    const int* __restrict__ count, const float* __restrict__ bias,
    const int* __restrict__ batch, float* __restrict__ pool, float* __restrict__ cnt)
{
    int n = blockIdx.x * 8 + (threadIdx.x >> 5);
    int lane = threadIdx.x & 31;
    if (n >= N_NODES) return;
    float4 acc = gather_node(H, rowptr, csr_src, count, bias, n, lane);
    int g = __ldg(batch + n);
    red_add_v4(pool + (size_t)g * HID + lane * 4, acc.x, acc.y, acc.z, acc.w);
    if (lane == 0) atomicAdd(&cnt[g], 1.0f);
}

// ---------------- finalize ----------------
__global__ void finalize_kernel(const float* __restrict__ pool, const float* __restrict__ cnt,
                                float* __restrict__ out)
{
    int i = blockIdx.x * blockDim.x + threadIdx.x;
    if (i >= N_GRAPHS * HID) return;
    int g = i >> 7;
    out[i] = pool[i] / fmaxf(cnt[g], 1.0f);
}

// ---------------- launch ----------------
extern "C" void kernel_launch(void* const* d_in, const int* in_sizes, int n_in,
                              void* d_out, int out_size)
{
    const float* drug_x = (const float*)d_in[0];
    const float* W1     = (const float*)d_in[1];
    const float* b1     = (const float*)d_in[2];
    const float* W2     = (const float*)d_in[3];
    const float* b2     = (const float*)d_in[4];
    const int*   eidx   = (const int*)d_in[5];
    const int*   batch  = (const int*)d_in[6];
    float* out = (float*)d_out;

    const int* src = eidx;
    const int* dst = eidx + N_EDGES;

    __half *bufH, *bufH2, *bufC;
    float *pool, *cnt;
    int *count, *rowptr, *cursor, *csr_src;
    unsigned long long* tilestate;
    __nv_bfloat16 *wth, *wtl;
    cudaGetSymbolAddress((void**)&bufH,  g_bufH);
    cudaGetSymbolAddress((void**)&bufH2, g_bufH2);
    cudaGetSymbolAddress((void**)&bufC,  g_bufC);
    cudaGetSymbolAddress((void**)&pool, g_pool);
    cudaGetSymbolAddress((void**)&cnt,  g_cnt);
    cudaGetSymbolAddress((void**)&count,  g_count);
    cudaGetSymbolAddress((void**)&rowptr, g_rowptr);
    cudaGetSymbolAddress((void**)&cursor, g_cursor);
    cudaGetSymbolAddress((void**)&csr_src, g_csr_src);
    cudaGetSymbolAddress((void**)&tilestate, g_tilestate);
    cudaGetSymbolAddress((void**)&wth, g_wt_hi);
    cudaGetSymbolAddress((void**)&wtl, g_wt_lo);

    static cudaStream_t s2 = nullptr;
    static cudaEvent_t evFork = nullptr, evJoin = nullptr, evW = nullptr,
                       evH = nullptr, evA = nullptr, evA2 = nullptr;
    if (!s2) {
        cudaStreamCreateWithFlags(&s2, cudaStreamNonBlocking);
        cudaEventCreateWithFlags(&evFork, cudaEventDisableTiming);
        cudaEventCreateWithFlags(&evJoin, cudaEventDisableTiming);
        cudaEventCreateWithFlags(&evW, cudaEventDisableTiming);
        cudaEventCreateWithFlags(&evH, cudaEventDisableTiming);
        cudaEventCreateWithFlags(&evA, cudaEventDisableTiming);
        cudaEventCreateWithFlags(&evA2, cudaEventDisableTiming);
        cudaFuncSetAttribute(gemm_mma_kernel<false>,
                             cudaFuncAttributeMaxDynamicSharedMemorySize, SM_GEMM_TOTAL);
        cudaFuncSetAttribute(gemm_mma_kernel<true>,
                             cudaFuncAttributeMaxDynamicSharedMemorySize, SM_GEMM_TOTAL);
    }

    const int T = 256;
    int gemm_blocks_full = (N_NODES + 127) / 128;   // 391
    int gemm_blocks_half = (HALF_N + 127) / 128;    // 196
    int gath_blocks_half = (HALF_N + 7) / 8;        // 3125
    int gath_blocks_full = (N_NODES + 7) / 8;       // 6250

    // fork FIRST (capture-legal): s2 enters the capture via evFork
    cudaEventRecord(evFork, 0);
    cudaStreamWaitEvent(s2, evFork, 0);

    // s2 branch: wprep (overlaps init+hist)
    wprep_kernel<<<dim3((HID * HID + T - 1) / T, 2), T, 0, s2>>>(W1, W2, wth, wtl);
    cudaEventRecord(evW, s2);

    // main branch: init -> hist
    init_kernel<<<(N_GRAPHS * HID + T - 1) / T, T>>>(pool, cnt, count, tilestate);
    hist_kernel<<<(N_EDGES / 4 + T - 1) / T, T>>>(dst, count);
    cudaEventRecord(evH, 0);

    // s2: scan + fill (need hist's count)
    cudaStreamWaitEvent(s2, evH, 0);
    scan_fused_kernel<<<SCAN_B, SCAN_T, 0, s2>>>(count, rowptr, cursor, tilestate);
    fill_kernel<<<(N_EDGES + T - 1) / T, T, 0, s2>>>(src, dst, cursor, csr_src);
    cudaEventRecord(evJoin, s2);

    // main: gemm1 -> bufH (needs weights from s2 wprep + count from hist)
    cudaStreamWaitEvent(0, evW, 0);
    gemm_mma_kernel<false><<<gemm_blocks_full, T, SM_GEMM_TOTAL>>>(drug_x, wth, wtl, count,
                                                                   bufH, 0, N_NODES);
    cudaStreamWaitEvent(0, evJoin, 0);

    // pipeline: gather1_A -> {gemm2_A (bufC->bufH2) on s2 || gather1_B on main} -> gemm2_B
    // RACE-FREE: gemm2 writes bufH2 while gather1_B reads bufH (disjoint buffers).
    gather_kernel<<<gath_blocks_half, T>>>(bufH, bufC, rowptr, csr_src, count, b1,
                                           0, HALF_N);
    cudaEventRecord(evA, 0);
    cudaStreamWaitEvent(s2, evA, 0);
    gemm_mma_kernel<true><<<gemm_blocks_half, T, SM_GEMM_TOTAL, s2>>>(
        bufC, wth + HID * HID, wtl + HID * HID, count, bufH2, 0, HALF_N);
    cudaEventRecord(evA2, s2);

    gather_kernel<<<gath_blocks_half, T>>>(bufH, bufC, rowptr, csr_src, count, b1,
                                           HALF_N, N_NODES);
    gemm_mma_kernel<true><<<gemm_blocks_half, T, SM_GEMM_TOTAL>>>(
        bufC, wth + HID * HID, wtl + HID * HID, count, bufH2, HALF_N, N_NODES);
    cudaStreamWaitEvent(0, evA2, 0);

    gather_pool_kernel<<<gath_blocks_full, T>>>(bufH2, rowptr, csr_src, count, b2,
                                                batch, pool, cnt);
    finalize_kernel<<<(N_GRAPHS * HID + T - 1) / T, T>>>(pool, cnt, out);
}

// round 16
// speedup vs baseline: 1.0684x; 1.0684x over previous
#include <cuda_runtime.h>
#include <cuda_bf16.h>
#include <cuda_fp16.h>
#include <cstdint>

#define N_NODES 50000
#define N_EDGES 600000
#define N_GRAPHS 1000
#define HID 128
#define NEG_SLOPE 0.01f

#define SCH 8
#define SCAN_T 256
#define SCAN_TILE (SCAN_T * SCH)                         // 2048
#define SCAN_B ((N_NODES + SCAN_TILE - 1) / SCAN_TILE)   // 25 (<=32: 1-window lookback)

// ---------------- scratch (static device globals; no allocation) ----------------
__device__ __half g_bufH[(size_t)N_NODES * HID];   // GEMM output (unscaled), fp16
__device__ __half g_bufC[(size_t)N_NODES * HID];   // layer-1 activated output, fp16
__device__ float  g_dinv[N_NODES];
__device__ float  g_pool[N_GRAPHS * HID];
__device__ float  g_cnt[N_GRAPHS];
__device__ int    g_count[N_NODES];
__device__ int    g_rowptr[N_NODES + 1];
__device__ int    g_cursor[N_NODES];
__device__ int    g_csr_src[N_EDGES];
__device__ unsigned long long g_tilestate[32];
__device__ __nv_bfloat16 g_wt_hi[2][HID * HID];
__device__ __nv_bfloat16 g_wt_lo[2][HID * HID];

// ---------------- helpers ----------------
__device__ __forceinline__ float leaky(float x) {
    return x > 0.0f ? x : NEG_SLOPE * x;
}

__device__ __forceinline__ void red_add_v4(float* addr, float a, float b, float c, float d) {
    asm volatile("red.global.add.v4.f32 [%0], {%1, %2, %3, %4};"
                 :: "l"(addr), "f"(a), "f"(b), "f"(c), "f"(d) : "memory");
}

__device__ __forceinline__ float4 ld_half4(const __half* p) {
    uint2 u = __ldg((const uint2*)p);
    __half2 h0 = *reinterpret_cast<__half2*>(&u.x);
    __half2 h1 = *reinterpret_cast<__half2*>(&u.y);
    float2 f0 = __half22float2(h0);
    float2 f1 = __half22float2(h1);
    return make_float4(f0.x, f0.y, f1.x, f1.y);
}

__device__ __forceinline__ void mma_bf16(float* d,
                                         uint32_t a0, uint32_t a1, uint32_t a2, uint32_t a3,
                                         uint32_t b0, uint32_t b1) {
    asm volatile("mma.sync.aligned.m16n8k16.row.col.f32.bf16.bf16.f32 "
                 "{%0,%1,%2,%3}, {%4,%5,%6,%7}, {%8,%9}, {%0,%1,%2,%3};"
                 : "+f"(d[0]), "+f"(d[1]), "+f"(d[2]), "+f"(d[3])
                 : "r"(a0), "r"(a1), "r"(a2), "r"(a3), "r"(b0), "r"(b1));
}

// ---------------- init ----------------
__global__ void init_kernel(float* pool, float* cnt, int* count,
                            unsigned long long* tilestate) {
    int i = blockIdx.x * blockDim.x + threadIdx.x;
    if (i < N_GRAPHS * HID) pool[i] = 0.0f;
    if (i < N_NODES) count[i] = 0;
    if (i < N_GRAPHS) cnt[i] = 0.0f;
    if (i < 32) tilestate[i] = 0ull;
}

// ---------------- degree histogram over dst ----------------
__global__ void hist_kernel(const int* __restrict__ dst, int* __restrict__ count) {
    int t = blockIdx.x * blockDim.x + threadIdx.x;
    if (t >= N_EDGES / 4) return;
    int4 d = __ldg((const int4*)dst + t);
    atomicAdd(&count[d.x], 1);
    atomicAdd(&count[d.y], 1);
    atomicAdd(&count[d.z], 1);
    atomicAdd(&count[d.w], 1);
}

// ---------------- single-pass scan (1-window lookback) + dinv ----------------
__global__ __launch_bounds__(SCAN_T) void scan_fused_kernel(
    const int* __restrict__ count, float* __restrict__ dinv,
    int* __restrict__ rowptr, int* __restrict__ cursor,
    unsigned long long* __restrict__ tilestate)
{
    __shared__ int warptot[SCAN_T / 32];
    __shared__ int s_base;
    const int bid = blockIdx.x;
    const int tid = threadIdx.x;
    const int base = bid * SCAN_TILE + tid * SCH;

    int pre[SCH];
    int s = 0;
#pragma unroll
    for (int q = 0; q < SCH; q++) {
        int idx = base + q;
        int c = (idx < N_NODES) ? __ldg(count + idx) : 0;
        if (idx < N_NODES) dinv[idx] = rsqrtf((float)c + 1.0f);
        pre[q] = s;
        s += c;
    }

    int lane = tid & 31, w = tid >> 5;
    int x = s;
#pragma unroll
    for (int off = 1; off < 32; off <<= 1) {
        int y = __shfl_up_sync(0xffffffffu, x, off);
        if (lane >= off) x += y;
    }
    if (lane == 31) warptot[w] = x;
    __syncthreads();
    if (tid < SCAN_T / 32) {
        int t2 = warptot[tid];
#pragma unroll
        for (int off = 1; off < SCAN_T / 32; off <<= 1) {
            int y = __shfl_up_sync(0xffu, t2, off);
            if ((int)tid >= off) t2 += y;
        }
        warptot[tid] = t2;
    }
    __syncthreads();
    int thread_excl = x - s + (w > 0 ? warptot[w - 1] : 0);
    int S = warptot[SCAN_T / 32 - 1];

    if (tid == 0) {
        unsigned long long pk = (bid == 0)
            ? ((2ull << 32) | (unsigned int)S)
            : ((1ull << 32) | (unsigned int)S);
        atomicExch(&tilestate[bid], pk);
        if (bid == 0) s_base = 0;
    }

    if (bid > 0 && w == 0) {
        int k = bid - 1 - lane;
        unsigned long long pk;
        int st, val;
        do {
            pk = (k >= 0) ? *((volatile unsigned long long*)&tilestate[k]) : (2ull << 32);
            st = (int)(pk >> 32);
            val = (int)(unsigned int)pk;
        } while (__any_sync(0xffffffffu, st == 0) || !__ballot_sync(0xffffffffu, st == 2));
        unsigned pm = __ballot_sync(0xffffffffu, st == 2);
        int L = __ffs(pm) - 1;
        int contrib = (lane <= L) ? val : 0;
#pragma unroll
        for (int off = 16; off > 0; off >>= 1)
            contrib += __shfl_down_sync(0xffffffffu, contrib, off);
        int base2 = __shfl_sync(0xffffffffu, contrib, 0);
        if (lane == 0) {
            s_base = base2;
            atomicExch(&tilestate[bid], (2ull << 32) | (unsigned int)(base2 + S));
        }
    }
    __syncthreads();

    int excl0 = s_base + thread_excl;
#pragma unroll
    for (int q = 0; q < SCH; q++) {
        int idx = base + q;
        if (idx < N_NODES) {
            rowptr[idx] = excl0 + pre[q];
            cursor[idx] = excl0 + pre[q];
        }
    }
    if (bid == 0 && tid == 0) rowptr[N_NODES] = N_EDGES;
}

// ---------------- fill CSR: src only, 1 edge/thread ----------------
__global__ void fill_kernel(const int* __restrict__ src, const int* __restrict__ dst,
                            int* __restrict__ cursor, int* __restrict__ csr_src)
{
    int e = blockIdx.x * blockDim.x + threadIdx.x;
    if (e >= N_EDGES) return;
    int s = __ldg(src + e);
    int d = __ldg(dst + e);
    int p = atomicAdd(&cursor[d], 1);
    csr_src[p] = s;
}

// ---------------- W prep (both layers; blockIdx.y = layer) ----------------
__global__ void wprep_kernel(const float* __restrict__ W1, const float* __restrict__ W2,
                             __nv_bfloat16* __restrict__ wt_hi,
                             __nv_bfloat16* __restrict__ wt_lo)
{
    int i = blockIdx.x * blockDim.x + threadIdx.x;
    if (i >= HID * HID) return;
    int layer = blockIdx.y;
    const float* W = layer ? W2 : W1;
    int n = i & 127, k = i >> 7;
    float v = W[i];
    __nv_bfloat16 h = __float2bfloat16(v);
    wt_hi[layer * HID * HID + n * HID + k] = h;
    wt_lo[layer * HID * HID + n * HID + k] = __float2bfloat16(v - __bfloat162float(h));
}

// ---------------- warp-MMA GEMM: H(fp16) = X*W (pure, no graph deps) ----------------
#define AS 132
#define SM_AH 0
#define SM_AL (SM_AH + 128 * AS * 2)
#define SM_BH (SM_AL + 128 * AS * 2)
#define SM_BL (SM_BH + 128 * AS * 2)
#define SM_GEMM_TOTAL (SM_BL + 128 * AS * 2)   // 135168 B

template <bool FP16IN>
__global__ __launch_bounds__(256) void gemm_mma_kernel(
    const void* __restrict__ Xv,
    const __nv_bfloat16* __restrict__ wt_hi,
    const __nv_bfloat16* __restrict__ wt_lo,
    __half* __restrict__ H, int M)
{
    extern __shared__ char smem[];
    const int tid = threadIdx.x;
    const int wid = tid >> 5;
    const int lane = tid & 31;
    const int rowBase = blockIdx.x * 128;

    {
        int row = tid >> 1;
        int half_ = tid & 1;
        int gr = rowBase + row;
        char* ah = smem + SM_AH + row * (AS * 2) + half_ * 128;
        char* al = smem + SM_AL + row * (AS * 2) + half_ * 128;
#pragma unroll
        for (int k4 = 0; k4 < 16; k4++) {
            float4 v;
            if (FP16IN) {
                const __half* xr = (const __half*)Xv + (size_t)gr * HID + half_ * 64;
                if (gr < M) v = ld_half4(xr + k4 * 4);
                else v = make_float4(0.f, 0.f, 0.f, 0.f);
            } else {
                const float4* xr = (const float4*)((const float*)Xv + (size_t)gr * HID) + half_ * 16;
                v = (gr < M) ? __ldg(&xr[k4]) : make_float4(0.f, 0.f, 0.f, 0.f);
            }
            __nv_bfloat16 h0 = __float2bfloat16(v.x), h1 = __float2bfloat16(v.y);
            __nv_bfloat16 h2 = __float2bfloat16(v.z), h3 = __float2bfloat16(v.w);
            __nv_bfloat16 l0 = __float2bfloat16(v.x - __bfloat162float(h0));
            __nv_bfloat16 l1 = __float2bfloat16(v.y - __bfloat162float(h1));
            __nv_bfloat16 l2 = __float2bfloat16(v.z - __bfloat162float(h2));
            __nv_bfloat16 l3 = __float2bfloat16(v.w - __bfloat162float(h3));
            uint2 hp, lp;
            hp.x = (uint32_t)__bfloat16_as_ushort(h0) | ((uint32_t)__bfloat16_as_ushort(h1) << 16);
            hp.y = (uint32_t)__bfloat16_as_ushort(h2) | ((uint32_t)__bfloat16_as_ushort(h3) << 16);
            lp.x = (uint32_t)__bfloat16_as_ushort(l0) | ((uint32_t)__bfloat16_as_ushort(l1) << 16);
            lp.y = (uint32_t)__bfloat16_as_ushort(l2) | ((uint32_t)__bfloat16_as_ushort(l3) << 16);
            *(uint2*)(ah + k4 * 8) = hp;
            *(uint2*)(al + k4 * 8) = lp;
        }
    }
    {
        const uint32_t* gh = (const uint32_t*)wt_hi;
        const uint32_t* gl = (const uint32_t*)wt_lo;
#pragma unroll
        for (int w = 0; w < 32; w++) {
            int wi = tid + w * 256;
            int r = wi >> 6, c = wi & 63;
            *(uint32_t*)(smem + SM_BH + r * (AS * 2) + c * 4) = __ldg(&gh[r * 64 + c]);
            *(uint32_t*)(smem + SM_BL + r * (AS * 2) + c * 4) = __ldg(&gl[r * 64 + c]);
        }
    }
    __syncthreads();

    const int g = lane >> 2, t = lane & 3;
    const int mOff = (wid & 3) * 32;
    const int nOff = (wid >> 2) * 64;

    float acc[2][8][4];
#pragma unroll
    for (int i = 0; i < 2; i++)
#pragma unroll
        for (int j = 0; j < 8; j++)
#pragma unroll
            for (int q = 0; q < 4; q++) acc[i][j][q] = 0.0f;

#pragma unroll
    for (int ks = 0; ks < 8; ks++) {
        int k0 = ks * 16;
        uint32_t ah[2][4], al[2][4];
#pragma unroll
        for (int i = 0; i < 2; i++) {
            int r0 = mOff + i * 16 + g;
            const char* pah = smem + SM_AH;
            const char* pal = smem + SM_AL;
            ah[i][0] = *(const uint32_t*)(pah + (r0)     * (AS * 2) + (k0 + t * 2) * 2);
            ah[i][1] = *(const uint32_t*)(pah + (r0 + 8) * (AS * 2) + (k0 + t * 2) * 2);
            ah[i][2] = *(const uint32_t*)(pah + (r0)     * (AS * 2) + (k0 + t * 2 + 8) * 2);
            ah[i][3] = *(const uint32_t*)(pah + (r0 + 8) * (AS * 2) + (k0 + t * 2 + 8) * 2);
            al[i][0] = *(const uint32_t*)(pal + (r0)     * (AS * 2) + (k0 + t * 2) * 2);
            al[i][1] = *(const uint32_t*)(pal + (r0 + 8) * (AS * 2) + (k0 + t * 2) * 2);
            al[i][2] = *(const uint32_t*)(pal + (r0)     * (AS * 2) + (k0 + t * 2 + 8) * 2);
            al[i][3] = *(const uint32_t*)(pal + (r0 + 8) * (AS * 2) + (k0 + t * 2 + 8) * 2);
        }
#pragma unroll
        for (int j = 0; j < 8; j++) {
            int n0 = nOff + j * 8 + g;
            uint32_t bh0 = *(const uint32_t*)(smem + SM_BH + n0 * (AS * 2) + (k0 + t * 2) * 2);
            uint32_t bh1 = *(const uint32_t*)(smem + SM_BH + n0 * (AS * 2) + (k0 + t * 2 + 8) * 2);
            uint32_t bl0 = *(const uint32_t*)(smem + SM_BL + n0 * (AS * 2) + (k0 + t * 2) * 2);
            uint32_t bl1 = *(const uint32_t*)(smem + SM_BL + n0 * (AS * 2) + (k0 + t * 2 + 8) * 2);
#pragma unroll
            for (int i = 0; i < 2; i++) {
                mma_bf16(acc[i][j], ah[i][0], ah[i][1], ah[i][2], ah[i][3], bh0, bh1);
                mma_bf16(acc[i][j], ah[i][0], ah[i][1], ah[i][2], ah[i][3], bl0, bl1);
                mma_bf16(acc[i][j], al[i][0], al[i][1], al[i][2], al[i][3], bh0, bh1);
            }
        }
    }

#pragma unroll
    for (int i = 0; i < 2; i++) {
#pragma unroll
        for (int j = 0; j < 8; j++) {
            int row = rowBase + mOff + i * 16 + g;
            int col = nOff + j * 8 + t * 2;
            if (row < M)
                *(__half2*)(H + (size_t)row * HID + col) =
                    __floats2half2_rn(acc[i][j][0], acc[i][j][1]);
            if (row + 8 < M)
                *(__half2*)(H + (size_t)(row + 8) * HID + col) =
                    __floats2half2_rn(acc[i][j][2], acc[i][j][3]);
        }
    }
}

// ---------------- gather core: out = leaky( dn*(sum_e ds*h[s] + dn*h[n]) + b ) ----------
__device__ __forceinline__ float4 gather_node(
    const __half* __restrict__ H, const int* __restrict__ rowptr,
    const int* __restrict__ csr_src, const float* __restrict__ dinv,
    const float* __restrict__ bias, int n, int lane)
{
    float dn = __ldg(dinv + n);
    float4 h = ld_half4(H + (size_t)n * HID + lane * 4);
    float4 acc = make_float4(dn * h.x, dn * h.y, dn * h.z, dn * h.w);  // dn*h[n]

    int i   = __ldg(rowptr + n);
    int end = __ldg(rowptr + n + 1);

    for (; i + 4 <= end; i += 4) {
        int s0 = __ldg(csr_src + i + 0);
        int s1 = __ldg(csr_src + i + 1);
        int s2 = __ldg(csr_src + i + 2);
        int s3 = __ldg(csr_src + i + 3);
        float d0 = __ldg(dinv + s0);
        float d1 = __ldg(dinv + s1);
        float d2 = __ldg(dinv + s2);
        float d3 = __ldg(dinv + s3);
        float4 v0 = ld_half4(H + (size_t)s0 * HID + lane * 4);
        float4 v1 = ld_half4(H + (size_t)s1 * HID + lane * 4);
        float4 v2 = ld_half4(H + (size_t)s2 * HID + lane * 4);
        float4 v3 = ld_half4(H + (size_t)s3 * HID + lane * 4);
        acc.x = fmaf(d0, v0.x, acc.x); acc.y = fmaf(d0, v0.y, acc.y);
        acc.z = fmaf(d0, v0.z, acc.z); acc.w = fmaf(d0, v0.w, acc.w);
        acc.x = fmaf(d1, v1.x, acc.x); acc.y = fmaf(d1, v1.y, acc.y);
        acc.z = fmaf(d1, v1.z, acc.z); acc.w = fmaf(d1, v1.w, acc.w);
        acc.x = fmaf(d2, v2.x, acc.x); acc.y = fmaf(d2, v2.y, acc.y);
        acc.z = fmaf(d2, v2.z, acc.z); acc.w = fmaf(d2, v2.w, acc.w);
        acc.x = fmaf(d3, v3.x, acc.x); acc.y = fmaf(d3, v3.y, acc.y);
        acc.z = fmaf(d3, v3.z, acc.z); acc.w = fmaf(d3, v3.w, acc.w);
    }
    for (; i < end; i++) {
        int s = __ldg(csr_src + i);
        float ds = __ldg(dinv + s);
        float4 v = ld_half4(H + (size_t)s * HID + lane * 4);
        acc.x = fmaf(ds, v.x, acc.x); acc.y = fmaf(ds, v.y, acc.y);
        acc.z = fmaf(ds, v.z, acc.z); acc.w = fmaf(ds, v.w, acc.w);
    }

    float4 b = *(const float4*)(bias + lane * 4);
    acc.x = leaky(fmaf(dn, acc.x, b.x));
    acc.y = leaky(fmaf(dn, acc.y, b.y));
    acc.z = leaky(fmaf(dn, acc.z, b.z));
    acc.w = leaky(fmaf(dn, acc.w, b.w));
    return acc;
}

// layer-1 gather: write activated fp16 features
__global__ __launch_bounds__(256) void gather_kernel(
    const __half* __restrict__ H, __half* __restrict__ OUT,
    const int* __restrict__ rowptr, const int* __restrict__ csr_src,
    const float* __restrict__ dinv, const float* __restrict__ bias)
{
    int n = blockIdx.x * 8 + (threadIdx.x >> 5);
    int lane = threadIdx.x & 31;
    if (n >= N_NODES) return;
    float4 acc = gather_node(H, rowptr, csr_src, dinv, bias, n, lane);
    __half2 o0 = __floats2half2_rn(acc.x, acc.y);
    __half2 o1 = __floats2half2_rn(acc.z, acc.w);
    uint2 u;
    u.x = *reinterpret_cast<uint32_t*>(&o0);
    u.y = *reinterpret_cast<uint32_t*>(&o1);
    *(uint2*)(OUT + (size_t)n * HID + lane * 4) = u;
}

// layer-2 gather fused with mean-pool accumulation
__global__ __launch_bounds__(256) void gather_pool_kernel(
    const __half* __restrict__ H,
    const int* __restrict__ rowptr, const int* __restrict__ csr_src,
    const float* __restrict__ dinv, const float* __restrict__ bias,
    const int* __restrict__ batch, float* __restrict__ pool, float* __restrict__ cnt)
{
    int n = blockIdx.x * 8 + (threadIdx.x >> 5);
    int lane = threadIdx.x & 31;
    if (n >= N_NODES) return;
    float4 acc = gather_node(H, rowptr, csr_src, dinv, bias, n, lane);
    int g = __ldg(batch + n);
    red_add_v4(pool + (size_t)g * HID + lane * 4, acc.x, acc.y, acc.z, acc.w);
    if (lane == 0) atomicAdd(&cnt[g], 1.0f);
}

// ---------------- finalize ----------------
__global__ void finalize_kernel(const float* __restrict__ pool, const float* __restrict__ cnt,
                                float* __restrict__ out)
{
    int i = blockIdx.x * blockDim.x + threadIdx.x;
    if (i >= N_GRAPHS * HID) return;
    int g = i >> 7;
    out[i] = pool[i] / fmaxf(cnt[g], 1.0f);
}

// ---------------- launch ----------------
extern "C" void kernel_launch(void* const* d_in, const int* in_sizes, int n_in,
                              void* d_out, int out_size)
{
    const float* drug_x = (const float*)d_in[0];
    const float* W1     = (const float*)d_in[1];
    const float* b1     = (const float*)d_in[2];
    const float* W2     = (const float*)d_in[3];
    const float* b2     = (const float*)d_in[4];
    const int*   eidx   = (const int*)d_in[5];
    const int*   batch  = (const int*)d_in[6];
    float* out = (float*)d_out;

    const int* src = eidx;
    const int* dst = eidx + N_EDGES;

    __half *bufH, *bufC;
    float *dinv, *pool, *cnt;
    int *count, *rowptr, *cursor, *csr_src;
    unsigned long long* tilestate;
    __nv_bfloat16 *wth, *wtl;
    cudaGetSymbolAddress((void**)&bufH, g_bufH);
    cudaGetSymbolAddress((void**)&bufC, g_bufC);
    cudaGetSymbolAddress((void**)&dinv, g_dinv);
    cudaGetSymbolAddress((void**)&pool, g_pool);
    cudaGetSymbolAddress((void**)&cnt,  g_cnt);
    cudaGetSymbolAddress((void**)&count,  g_count);
    cudaGetSymbolAddress((void**)&rowptr, g_rowptr);
    cudaGetSymbolAddress((void**)&cursor, g_cursor);
    cudaGetSymbolAddress((void**)&csr_src, g_csr_src);
    cudaGetSymbolAddress((void**)&tilestate, g_tilestate);
    cudaGetSymbolAddress((void**)&wth, g_wt_hi);
    cudaGetSymbolAddress((void**)&wtl, g_wt_lo);

    static cudaStream_t s2 = nullptr;
    static cudaEvent_t evFork = nullptr, evJoin = nullptr;
    if (!s2) {
        cudaStreamCreateWithFlags(&s2, cudaStreamNonBlocking);
        cudaEventCreateWithFlags(&evFork, cudaEventDisableTiming);
        cudaEventCreateWithFlags(&evJoin, cudaEventDisableTiming);
        cudaFuncSetAttribute(gemm_mma_kernel<false>,
                             cudaFuncAttributeMaxDynamicSharedMemorySize, SM_GEMM_TOTAL);
        cudaFuncSetAttribute(gemm_mma_kernel<true>,
                             cudaFuncAttributeMaxDynamicSharedMemorySize, SM_GEMM_TOTAL);
    }

    const int T = 256;
    int gemm_blocks = (N_NODES + 127) / 128;   // 391
    int gath_blocks = (N_NODES + 7) / 8;       // 6250

    // fork FIRST (capture-legal): the ENTIRE CSR chain lives on s2;
    // main runs wprep + gemm1 which have no graph dependencies (R9 structure).
    cudaEventRecord(evFork, 0);
    cudaStreamWaitEvent(s2, evFork, 0);

    init_kernel<<<(N_GRAPHS * HID + T - 1) / T, T, 0, s2>>>(pool, cnt, count, tilestate);
    hist_kernel<<<(N_EDGES / 4 + T - 1) / T, T, 0, s2>>>(dst, count);
    scan_fused_kernel<<<SCAN_B, SCAN_T, 0, s2>>>(count, dinv, rowptr, cursor, tilestate);
    fill_kernel<<<(N_EDGES + T - 1) / T, T, 0, s2>>>(src, dst, cursor, csr_src);
    cudaEventRecord(evJoin, s2);

    // main: wprep -> gemm1 (pure GEMM)
    wprep_kernel<<<dim3((HID * HID + T - 1) / T, 2), T>>>(W1, W2, wth, wtl);
    gemm_mma_kernel<false><<<gemm_blocks, T, SM_GEMM_TOTAL>>>(drug_x, wth, wtl, bufH, N_NODES);
    cudaStreamWaitEvent(0, evJoin, 0);

    // serial tail (full-grid kernels, no split)
    gather_kernel<<<gath_blocks, T>>>(bufH, bufC, rowptr, csr_src, dinv, b1);
    gemm_mma_kernel<true><<<gemm_blocks, T, SM_GEMM_TOTAL>>>(bufC, wth + HID * HID,
                                                             wtl + HID * HID, bufH, N_NODES);
    gather_pool_kernel<<<gath_blocks, T>>>(bufH, rowptr, csr_src, dinv, b2, batch, pool, cnt);
    finalize_kernel<<<(N_GRAPHS * HID + T - 1) / T, T>>>(pool, cnt, out);
}